// round 5
// baseline (speedup 1.0000x reference)
#include <cuda_runtime.h>
#include <cstdint>
#include <math_constants.h>

#define NND 100000
#define NE  3200000
#define NG  128
#define NH  32
#define FULL 0xffffffffu

// ---------------- device scratch (allocation-free) ----------------
__device__ __align__(16) float  g_agg1[2 * NND];            // 0.8 MB
__device__ __align__(16) float2 g_tj  [2 * NND];            // 1.6 MB  (t, j-as-int)
__device__ __align__(16) float2 g_bkt [2LL * NND * 33];     // 52.8 MB (sum,count)/interval
__device__ __align__(16) float  g_pool[NG * NH];            // 16 KB (signed: g1 +, g2 -)
__device__ float g_th[NH];     // sorted thresholds
__device__ int   g_rank[NH];   // rank of threshold k in sorted order

// ---------------- int64 vs int32 index detection ----------------
__device__ __forceinline__ bool detect_int64(const void* p, long long nelem,
                                             unsigned long long maxval) {
    const long long* q = (const long long*)p;
    long long a = q[nelem / 2 - 1];
    long long b = q[nelem / 2 - 2];
    return ((unsigned long long)a < maxval) && ((unsigned long long)b < maxval);
}

// Load 8 consecutive edges (e % 8 == 0) with wide loads.
__device__ __forceinline__ void load_edge8(const void* ep, bool is64, long long e,
                                           int (&src)[8], int (&dst)[8]) {
    if (is64) {
        const longlong2* q = (const longlong2*)ep;
#pragma unroll
        for (int u = 0; u < 4; u++) {
            longlong2 s = q[(e >> 1) + u];
            longlong2 d = q[(((long long)NE + e) >> 1) + u];
            src[2 * u] = (int)s.x; src[2 * u + 1] = (int)s.y;
            dst[2 * u] = (int)d.x; dst[2 * u + 1] = (int)d.y;
        }
    } else {
        const int* qi = (const int*)ep;
#pragma unroll
        for (int u = 0; u < 2; u++) {
            int4 s = ((const int4*)qi)[(e >> 2) + u];
            int4 d = ((const int4*)(qi + NE))[(e >> 2) + u];
            src[4 * u] = s.x; src[4 * u + 1] = s.y; src[4 * u + 2] = s.z; src[4 * u + 3] = s.w;
            dst[4 * u] = d.x; dst[4 * u + 1] = d.y; dst[4 * u + 2] = d.z; dst[4 * u + 3] = d.w;
        }
    }
}

// ---------------- kernels ----------------

// Sort thresholds theta_k = -b1k/W1k (W==0 -> +INF), compute ranks. 1 warp.
__global__ void prep_kernel(const float* __restrict__ W1, const float* __restrict__ b1) {
    int lane = threadIdx.x;
    float w = W1[lane], b = b1[lane];
    float th = (w != 0.f) ? (-b / w) : CUDART_INF_F;
    int r = 0;
#pragma unroll
    for (int i = 0; i < NH; i++) {
        float o = __shfl_sync(FULL, th, i);
        r += (o < th) || (o == th && i < lane);
    }
    g_th[r] = th;
    g_rank[lane] = r;
}

// Zero accumulators (scratch persists across graph replays).
__global__ void zero_kernel() {
    long long i = (long long)blockIdx.x * blockDim.x + threadIdx.x;
    float4 z = make_float4(0.f, 0.f, 0.f, 0.f);
    const long long NB4 = 2LL * NND * 33 * 2 / 4;
    if (i < NB4)          ((float4*)g_bkt)[i] = z;
    if (i < 2 * NND / 4)  ((float4*)g_agg1)[i] = z;
    if (i < NG * NH / 4)  ((float4*)g_pool)[i] = z;
}

// Stage 1: agg1[dst] += x[src]. ILP-8.
__global__ void __launch_bounds__(256) edge1_kernel(
        const float* __restrict__ x1, const void* __restrict__ e1,
        const float* __restrict__ x2, const void* __restrict__ e2) {
    long long tid = (long long)blockIdx.x * blockDim.x + threadIdx.x;
    const long long NT = 2LL * NE / 8;
    if (tid >= NT) return;
    int g = (tid >= NT / 2);
    const void*  ep = g ? e2 : e1;
    const float* x  = g ? x2 : x1;
    bool is64 = detect_int64(ep, 2LL * NE, (unsigned long long)NND);
    long long e = (tid - (long long)g * (NT / 2)) * 8;

    int s[8], d[8];
    load_edge8(ep, is64, e, s, d);
    float xv[8];
#pragma unroll
    for (int u = 0; u < 8; u++) xv[u] = __ldg(&x[s[u]]);
    float* aggb = g_agg1 + g * NND;
#pragma unroll
    for (int u = 0; u < 8; u++) atomicAdd(&aggb[d[u]], xv[u]);
}

// t[i] = x[i] + agg1[i]; also precompute bucket index j = #(sorted th <= t)
// (once per NODE, so the 6.4M-edge pass needs no search). Store (t, j) packed.
__global__ void node_t_kernel(const float* __restrict__ x1, const float* __restrict__ x2) {
    __shared__ float th_s[32 * 32];
    for (int i = threadIdx.x; i < 32 * 32; i += blockDim.x) th_s[i] = g_th[i >> 5];
    __syncthreads();

    int i = blockIdx.x * blockDim.x + threadIdx.x;
    if (i >= 2 * NND) return;
    int g = (i >= NND);
    const float* x = g ? x2 : x1;
    float t = x[i - g * NND] + g_agg1[i];

    int lane = threadIdx.x & 31;
    int j = 0;
#pragma unroll
    for (int st = 16; st >= 1; st >>= 1) {
        int c = j + st;
        if (th_s[((c - 1) << 5) | lane] <= t) j = c;
    }
    if (j == 31 && th_s[(31 << 5) | lane] <= t) j = 32;

    g_tj[i] = make_float2(t, __int_as_float(j));
}

// Stage 2 (bucketed): one float2 atomic (t,1) per edge into bucket (dst, j(t_src)).
// ILP-8; j precomputed, so per edge: 1 scattered 8B gather + 1 scattered 8B RED.
__global__ void __launch_bounds__(256) edgeb_kernel(
        const void* __restrict__ e1, const void* __restrict__ e2) {
    long long tid = (long long)blockIdx.x * blockDim.x + threadIdx.x;
    const long long NT = 2LL * NE / 8;
    if (tid >= NT) return;
    int g = (tid >= NT / 2);
    const void* ep = g ? e2 : e1;
    bool is64 = detect_int64(ep, 2LL * NE, (unsigned long long)NND);
    long long e = (tid - (long long)g * (NT / 2)) * 8;

    int s[8], d[8];
    load_edge8(ep, is64, e, s, d);
    const float2* tjb = g_tj + g * NND;
    float2 tj[8];
#pragma unroll
    for (int u = 0; u < 8; u++) tj[u] = __ldg(&tjb[s[u]]);

    float2* bktb = g_bkt + (long long)g * NND * 33;
#pragma unroll
    for (int u = 0; u < 8; u++) {
        int j = __float_as_int(tj[u].y);
        atomicAdd(&bktb[(long long)d[u] * 33 + j], make_float2(tj[u].x, 1.f));
    }
}

// Stage 3 + layer2 + pool. Warp per 8 nodes: suffix-scan 32 interval buckets ->
// agg2[k] analytically; v = relu(t*W1+b1)+agg2; out = relu(v@W2+b2); pooled.
__global__ void __launch_bounds__(256) node_out_kernel(
        const void* __restrict__ bt1, const void* __restrict__ bt2,
        const float* __restrict__ W1, const float* __restrict__ b1,
        const float* __restrict__ W2, const float* __restrict__ b2) {
    const int CH = 8;
    const int chunks = NND / CH;  // 12500
    int lane = threadIdx.x & 31;
    int warp = (blockIdx.x * blockDim.x + threadIdx.x) >> 5;
    if (warp >= 2 * chunks) return;
    int g = (warp >= chunks);
    int c = warp - g * chunks;
    int start = c * CH;

    const void* bp = g ? bt2 : bt1;
    bool is64 = detect_int64(bp, (long long)NND, (unsigned long long)NG);
    float w1  = W1[lane];
    float bb1 = b1[lane];
    float bb2 = b2[lane];
    int   rnk = g_rank[lane];
    float sign = g ? -1.f : 1.f;
    float w2r[NH];
#pragma unroll
    for (int k = 0; k < NH; k++) w2r[k] = W2[k * NH + lane];

    const float2* tjb = g_tj + g * NND;
    float poolacc = 0.f;
    int curg = -1;

    for (int n = start; n < start + CH; n++) {
        const float2* bkt = &g_bkt[((long long)(g * NND + n)) * 33];
        float2 bv = bkt[1 + lane];       // intervals 1..32 on lanes 0..31
        float2 b0 = bkt[0];              // interval 0
        float ss = bv.x, cc = bv.y;
#pragma unroll
        for (int off = 1; off < 32; off <<= 1) {   // inclusive suffix scan
            float s2 = __shfl_down_sync(FULL, ss, off);
            float c2 = __shfl_down_sync(FULL, cc, off);
            if (lane + off < 32) { ss += s2; cc += c2; }
        }
        float TS = b0.x + __shfl_sync(FULL, ss, 0);
        float TC = b0.y + __shfl_sync(FULL, cc, 0);
        float mS = __shfl_sync(FULL, ss, rnk);
        float mC = __shfl_sync(FULL, cc, rnk);
        float agg;
        if (w1 > 0.f)       agg = w1 * mS + bb1 * mC;
        else if (w1 < 0.f)  agg = w1 * (TS - mS) + bb1 * (TC - mC);
        else                agg = fmaxf(bb1, 0.f) * TC;

        float t = tjb[n].x;
        float v = fmaxf(fmaf(t, w1, bb1), 0.f) + agg;

        float acc = bb2;
#pragma unroll
        for (int k = 0; k < NH; k++)
            acc = fmaf(__shfl_sync(FULL, v, k), w2r[k], acc);
        acc = fmaxf(acc, 0.f);

        int bg = is64 ? (int)((const long long*)bp)[n] : ((const int*)bp)[n];
        if (bg != curg) {
            if (curg >= 0) atomicAdd(&g_pool[curg * NH + lane], sign * poolacc);
            poolacc = 0.f;
            curg = bg;
        }
        poolacc += acc;
    }
    if (curg >= 0) atomicAdd(&g_pool[curg * NH + lane], sign * poolacc);
}

__global__ void abs_kernel(float* __restrict__ out) {
    int i = blockIdx.x * blockDim.x + threadIdx.x;
    if (i < NG * NH) out[i] = fabsf(g_pool[i]);
}

// ---------------- launch ----------------
extern "C" void kernel_launch(void* const* d_in, const int* in_sizes, int n_in,
                              void* d_out, int out_size) {
    const float* x1  = (const float*)d_in[0];
    const void*  ei1 = d_in[1];
    const void*  bt1 = d_in[2];
    const float* x2  = (const float*)d_in[3];
    const void*  ei2 = d_in[4];
    const void*  bt2 = d_in[5];
    const float* W1  = (const float*)d_in[6];
    const float* b1  = (const float*)d_in[7];
    const float* W2  = (const float*)d_in[8];
    const float* b2  = (const float*)d_in[9];
    float* out = (float*)d_out;

    prep_kernel<<<1, 32>>>(W1, b1);
    {
        long long n4 = 2LL * NND * 33 * 2 / 4;
        zero_kernel<<<(int)((n4 + 255) / 256), 256>>>();
    }
    {
        long long nt = 2LL * NE / 8;
        edge1_kernel<<<(int)((nt + 255) / 256), 256>>>(x1, ei1, x2, ei2);
    }
    node_t_kernel<<<(2 * NND + 255) / 256, 256>>>(x1, x2);
    {
        long long nt = 2LL * NE / 8;
        edgeb_kernel<<<(int)((nt + 255) / 256), 256>>>(ei1, ei2);
    }
    {
        int warps = 2 * (NND / 8);
        node_out_kernel<<<(warps * 32 + 255) / 256, 256>>>(bt1, bt2, W1, b1, W2, b2);
    }
    abs_kernel<<<(NG * NH + 255) / 256, 256>>>(out);
}

// round 6
// speedup vs baseline: 1.0618x; 1.0618x over previous
#include <cuda_runtime.h>
#include <cstdint>
#include <math_constants.h>

#define NND 100000
#define NE  3200000
#define NG  128
#define NH  32
#define FULL 0xffffffffu

// ---------------- device scratch (allocation-free) ----------------
__device__ __align__(16) float g_agg1[2 * NND];          // 0.8 MB
__device__ __align__(16) float g_t   [2 * NND];          // 0.8 MB   (t per node)
__device__ __align__(16) int   g_P   [2 * NND];          // 0.8 MB   packed (j<<25)|A
__device__ __align__(16) int   g_bkt [2LL * NND * 33];   // 26.4 MB  packed count/sum
__device__ __align__(16) float g_pool[NG * NH];          // 16 KB (signed: g1 +, g2 -)
__device__ float g_th[NH];     // sorted thresholds
__device__ int   g_rank[NH];   // rank of threshold k
__device__ unsigned int g_ctr; // node_out completion counter

// ---------------- int64 vs int32 index detection ----------------
__device__ __forceinline__ bool detect_int64(const void* p, long long nelem,
                                             unsigned long long maxval) {
    const long long* q = (const long long*)p;
    long long a = q[nelem / 2 - 1];
    long long b = q[nelem / 2 - 2];
    return ((unsigned long long)a < maxval) && ((unsigned long long)b < maxval);
}

// Load 4 consecutive edges (e % 4 == 0) with wide loads.
__device__ __forceinline__ void load_edge4(const void* ep, bool is64, long long e,
                                           int (&src)[4], int (&dst)[4]) {
    if (is64) {
        const longlong2* q = (const longlong2*)ep;
        longlong2 s0 = q[e >> 1], s1 = q[(e >> 1) + 1];
        longlong2 d0 = q[((long long)NE + e) >> 1], d1 = q[(((long long)NE + e) >> 1) + 1];
        src[0] = (int)s0.x; src[1] = (int)s0.y; src[2] = (int)s1.x; src[3] = (int)s1.y;
        dst[0] = (int)d0.x; dst[1] = (int)d0.y; dst[2] = (int)d1.x; dst[3] = (int)d1.y;
    } else {
        const int* qi = (const int*)ep;
        int4 s = ((const int4*)qi)[e >> 2];
        int4 d = ((const int4*)(qi + NE))[e >> 2];
        src[0] = s.x; src[1] = s.y; src[2] = s.z; src[3] = s.w;
        dst[0] = d.x; dst[1] = d.y; dst[2] = d.z; dst[3] = d.w;
    }
}

// ---------------- kernels ----------------

// Zero accumulators + (block 0, warp 0) sort thresholds / ranks + reset counter.
__global__ void zero_prep_kernel(const float* __restrict__ W1,
                                 const float* __restrict__ b1) {
    long long i = (long long)blockIdx.x * blockDim.x + threadIdx.x;
    int4 zi = make_int4(0, 0, 0, 0);
    const long long NB4 = 2LL * NND * 33 / 4;
    if (i < NB4)          ((int4*)g_bkt)[i] = zi;
    float4 zf = make_float4(0.f, 0.f, 0.f, 0.f);
    if (i < 2 * NND / 4)  ((float4*)g_agg1)[i] = zf;
    if (i < NG * NH / 4)  ((float4*)g_pool)[i] = zf;

    if (blockIdx.x == 0) {
        if (threadIdx.x == 32) g_ctr = 0;
        if (threadIdx.x < 32) {
            int lane = threadIdx.x;
            float w = W1[lane], b = b1[lane];
            float th = (w != 0.f) ? (-b / w) : CUDART_INF_F;
            int r = 0;
#pragma unroll
            for (int k = 0; k < NH; k++) {
                float o = __shfl_sync(FULL, th, k);
                r += (o < th) || (o == th && k < lane);
            }
            g_th[r] = th;
            g_rank[lane] = r;
        }
    }
}

// Stage 1: agg1[dst] += x[src]. ILP-4.
__global__ void __launch_bounds__(256) edge1_kernel(
        const float* __restrict__ x1, const void* __restrict__ e1,
        const float* __restrict__ x2, const void* __restrict__ e2) {
    long long tid = (long long)blockIdx.x * blockDim.x + threadIdx.x;
    const long long NT = 2LL * NE / 4;
    if (tid >= NT) return;
    int g = (tid >= NT / 2);
    const void*  ep = g ? e2 : e1;
    const float* x  = g ? x2 : x1;
    bool is64 = detect_int64(ep, 2LL * NE, (unsigned long long)NND);
    long long e = (tid - (long long)g * (NT / 2)) * 4;

    int s[4], d[4];
    load_edge4(ep, is64, e, s, d);
    float xv[4];
#pragma unroll
    for (int u = 0; u < 4; u++) xv[u] = __ldg(&x[s[u]]);
    float* aggb = g_agg1 + g * NND;
#pragma unroll
    for (int u = 0; u < 4; u++) atomicAdd(&aggb[d[u]], xv[u]);
}

// t[i] = x[i] + agg1[i]; bucket index j = #(sorted th <= t) in [0,32];
// pack payload P = (j<<25) | (2^24 + 2^17 + round(t*1024)).
__global__ void node_t_kernel(const float* __restrict__ x1, const float* __restrict__ x2) {
    __shared__ float th_s[32 * 32];
    for (int i = threadIdx.x; i < 32 * 32; i += blockDim.x) th_s[i] = g_th[i >> 5];
    __syncthreads();

    int i = blockIdx.x * blockDim.x + threadIdx.x;
    if (i >= 2 * NND) return;
    int g = (i >= NND);
    const float* x = g ? x2 : x1;
    float t = x[i - g * NND] + g_agg1[i];

    int lane = threadIdx.x & 31;
    int j = 0;
#pragma unroll
    for (int st = 16; st >= 1; st >>= 1) {
        int c = j + st;
        if (th_s[((c - 1) << 5) | lane] <= t) j = c;
    }
    if (j == 31 && th_s[(31 << 5) | lane] <= t) j = 32;

    int q = __float2int_rn(t * 1024.f);
    int A = (1 << 24) + (1 << 17) + q;
    g_t[i] = t;
    g_P[i] = (j << 25) | A;
}

// Stage 2: one RED.32 per edge: bkt[dst*33 + j] += A.  ILP-4, 4B gather of P[src].
__global__ void __launch_bounds__(256) edgeb_kernel(
        const void* __restrict__ e1, const void* __restrict__ e2) {
    long long tid = (long long)blockIdx.x * blockDim.x + threadIdx.x;
    const long long NT = 2LL * NE / 4;
    if (tid >= NT) return;
    int g = (tid >= NT / 2);
    const void* ep = g ? e2 : e1;
    bool is64 = detect_int64(ep, 2LL * NE, (unsigned long long)NND);
    long long e = (tid - (long long)g * (NT / 2)) * 4;

    int s[4], d[4];
    load_edge4(ep, is64, e, s, d);
    const int* Pb = g_P + g * NND;
    int P[4];
#pragma unroll
    for (int u = 0; u < 4; u++) P[u] = __ldg(&Pb[s[u]]);

    int* bktb = g_bkt + (long long)g * NND * 33;
#pragma unroll
    for (int u = 0; u < 4; u++) {
        int j = P[u] >> 25;
        int A = P[u] & 0x01FFFFFF;
        atomicAdd(&bktb[d[u] * 33 + j], A);
    }
}

// Stage 3 + layer2 + pool + final abs (last block). Warp per 8 nodes.
// Decode buckets: C = V>>24, S = ((V&0xFFFFFF) - C*2^17)/1024; suffix-scan ->
// agg2[k]; v = relu(t*W1+b1)+agg2; out = relu(v@W2+b2); pool by sorted batch.
__global__ void __launch_bounds__(256) node_out_kernel(
        const void* __restrict__ bt1, const void* __restrict__ bt2,
        const float* __restrict__ W1, const float* __restrict__ b1,
        const float* __restrict__ W2, const float* __restrict__ b2,
        float* __restrict__ out, int nblocks) {
    const int CH = 8;
    const int chunks = NND / CH;  // 12500
    int lane = threadIdx.x & 31;
    int warp = (blockIdx.x * blockDim.x + threadIdx.x) >> 5;
    // grid sized so warp < 2*chunks always; guard defensively without early return
    bool active = (warp < 2 * chunks);
    int g = 0, start = 0;
    if (active) {
        g = (warp >= chunks);
        start = (warp - g * chunks) * CH;
    }

    const void* bp = g ? bt2 : bt1;
    bool is64 = detect_int64(bp, (long long)NND, (unsigned long long)NG);
    float w1  = W1[lane];
    float bb1 = b1[lane];
    float bb2 = b2[lane];
    int   rnk = g_rank[lane];
    float sign = g ? -1.f : 1.f;
    float w2r[NH];
#pragma unroll
    for (int k = 0; k < NH; k++) w2r[k] = W2[k * NH + lane];

    if (active) {
        const float* tb = g_t + g * NND;
        float poolacc = 0.f;
        int curg = -1;

        for (int n = start; n < start + CH; n++) {
            const int* bkt = &g_bkt[((long long)(g * NND + n)) * 33];
            int V = bkt[1 + lane];   // intervals 1..32 on lanes 0..31
            int V0 = bkt[0];         // interval 0
            float cc = (float)(V >> 24);
            float ss = (float)((V & 0xFFFFFF) - ((V >> 24) << 17)) * (1.f / 1024.f);
#pragma unroll
            for (int off = 1; off < 32; off <<= 1) {   // inclusive suffix scan
                float s2 = __shfl_down_sync(FULL, ss, off);
                float c2 = __shfl_down_sync(FULL, cc, off);
                if (lane + off < 32) { ss += s2; cc += c2; }
            }
            float c0 = (float)(V0 >> 24);
            float s0 = (float)((V0 & 0xFFFFFF) - ((V0 >> 24) << 17)) * (1.f / 1024.f);
            float TS = s0 + __shfl_sync(FULL, ss, 0);
            float TC = c0 + __shfl_sync(FULL, cc, 0);
            float mS = __shfl_sync(FULL, ss, rnk);
            float mC = __shfl_sync(FULL, cc, rnk);
            float agg;
            if (w1 > 0.f)       agg = w1 * mS + bb1 * mC;
            else if (w1 < 0.f)  agg = w1 * (TS - mS) + bb1 * (TC - mC);
            else                agg = fmaxf(bb1, 0.f) * TC;

            float t = tb[n];
            float v = fmaxf(fmaf(t, w1, bb1), 0.f) + agg;

            float acc = bb2;
#pragma unroll
            for (int k = 0; k < NH; k++)
                acc = fmaf(__shfl_sync(FULL, v, k), w2r[k], acc);
            acc = fmaxf(acc, 0.f);

            int bg = is64 ? (int)((const long long*)bp)[n] : ((const int*)bp)[n];
            if (bg != curg) {
                if (curg >= 0) atomicAdd(&g_pool[curg * NH + lane], sign * poolacc);
                poolacc = 0.f;
                curg = bg;
            }
            poolacc += acc;
        }
        if (curg >= 0) atomicAdd(&g_pool[curg * NH + lane], sign * poolacc);
    }

    // last block writes |pool| to output
    __shared__ unsigned int s_last;
    __threadfence();
    __syncthreads();
    if (threadIdx.x == 0) {
        unsigned int done = atomicAdd(&g_ctr, 1u);
        s_last = (done == (unsigned int)(nblocks - 1)) ? 1u : 0u;
    }
    __syncthreads();
    if (s_last) {
        for (int i = threadIdx.x; i < NG * NH; i += blockDim.x)
            out[i] = fabsf(g_pool[i]);
    }
}

// ---------------- launch ----------------
extern "C" void kernel_launch(void* const* d_in, const int* in_sizes, int n_in,
                              void* d_out, int out_size) {
    const float* x1  = (const float*)d_in[0];
    const void*  ei1 = d_in[1];
    const void*  bt1 = d_in[2];
    const float* x2  = (const float*)d_in[3];
    const void*  ei2 = d_in[4];
    const void*  bt2 = d_in[5];
    const float* W1  = (const float*)d_in[6];
    const float* b1  = (const float*)d_in[7];
    const float* W2  = (const float*)d_in[8];
    const float* b2  = (const float*)d_in[9];
    float* out = (float*)d_out;

    {
        long long n4 = 2LL * NND * 33 / 4;
        zero_prep_kernel<<<(int)((n4 + 255) / 256), 256>>>(W1, b1);
    }
    {
        long long nt = 2LL * NE / 4;
        edge1_kernel<<<(int)((nt + 255) / 256), 256>>>(x1, ei1, x2, ei2);
    }
    node_t_kernel<<<(2 * NND + 255) / 256, 256>>>(x1, x2);
    {
        long long nt = 2LL * NE / 4;
        edgeb_kernel<<<(int)((nt + 255) / 256), 256>>>(ei1, ei2);
    }
    {
        int warps = 2 * (NND / 8);               // 25000
        int nblocks = (warps * 32 + 255) / 256;  // 3125
        node_out_kernel<<<nblocks, 256>>>(bt1, bt2, W1, b1, W2, b2, out, nblocks);
    }
}